// round 8
// baseline (speedup 1.0000x reference)
#include <cuda_runtime.h>
#include <cstdint>

// MultiScaleDeformableAttention — GB300
// value:              (8, 22223, 8, 32)  float32
// sampling_locations: (8, 900, 8, 4, 4, 2) float32
// attention_weights:  (8, 900, 8, 4, 4) float32
// out:                (8, 900, 256) float32
//
// Plateau diagnosis: ~3.7M L1tex wavefronts (64 distinct 128B lines per
// warp-task) bind the kernel at ~27us regardless of occupancy. Fix: CTA is
// pinned to one (b,h) (grid = 64 x 2 halves = 128 CTAs x 1024 thr), and the
// level-2+3 value planes (1323 keys x 128B = 169KB) are staged into dynamic
// smem once per CTA. The 8 lvl-2/3 taps per task then come from LDS.128
// (shared pipe, zero L1tex wavefronts); only the 8 lvl-0/1 taps stay LDG.

#define BS  8
#define NQ  900
#define NH  8
#define DC  32
#define NL  4
#define NPT 4
#define NKEYS 22223
#define KS4 (NH * DC / 4)        // float4s per key = 64
#define QHALF (NQ / 2)           // 450 queries per CTA
#define SKEY0 20900              // first staged key (level 2 start)
#define NSKEYS 1323              // keys in levels 2+3 (1050 + 273)
#define SMEM_F4 (NSKEYS * 8)     // 10584 float4s = 169344 bytes

__global__ __launch_bounds__(1024, 1) void msda_kernel(
    const float* __restrict__ value,
    const float* __restrict__ loc,
    const float* __restrict__ aw,
    float* __restrict__ out)
{
    extern __shared__ float4 s4[];   // [NSKEYS * 8]

    const int Hs[NL]     = {100, 50, 25, 13};
    const int Ws[NL]     = {167, 84, 42, 21};
    // per-level: base offset and float4 stride; lvl 0/1 global, lvl 2/3 smem
    const int bases[NL]  = {0, 16700, 0 /*20900-SKEY0*/, 1050 /*21950-SKEY0*/};

    const int bh   = blockIdx.x >> 1;    // 0..63
    const int half = blockIdx.x & 1;
    const int b    = bh >> 3;
    const int h    = bh & (NH - 1);

    const int tid  = threadIdx.x;
    const int wid  = tid >> 5;
    const int lane = tid & 31;
    const int g  = lane >> 3;            // point within level (0..3)
    const int cp = lane & 7;             // channel quad (0..7)

    // float4 base of value for (b, h): + key*KS4 (+cp for the tap lane)
    const float4* __restrict__ vb =
        (const float4*)value + ((size_t)(b * NKEYS) * NH + h) * (DC / 4);
    const float4* __restrict__ v4 = vb + cp;
    const float2* __restrict__ loc2 = (const float2*)loc;

    // ---- stage levels 2+3 into smem (coalesced) ----
    {
        const float4* __restrict__ src = vb + (size_t)SKEY0 * KS4;
        for (int i = tid; i < SMEM_F4; i += 1024) {
            const int key = i >> 3;
            const int j   = i & 7;
            s4[i] = __ldg(src + (size_t)key * KS4 + j);
        }
    }
    __syncthreads();

    for (int ql = wid; ql < QHALF; ql += 32) {
        const int q    = half * QHALF + ql;
        const int task = (b * NQ + q) * NH + h;

        // ---------------- Phase A: tap descriptors ----------------
        int   o00[NL], o10[NL], o01[NL], o11[NL];
        float w00[NL], w10[NL], w01[NL], w11[NL];

        #pragma unroll
        for (int lvl = 0; lvl < NL; ++lvl) {
            const int H = Hs[lvl];
            const int W = Ws[lvl];
            const int mult = (lvl < 2) ? KS4 : 8;   // global vs smem stride

            const int li = (task * NL + lvl) * NPT + g;
            const float2 l2 = __ldg(loc2 + li);
            const float w   = __ldg(aw + li);

            const float x = l2.x * (float)W - 0.5f;
            const float y = l2.y * (float)H - 0.5f;
            const float xf = floorf(x);
            const float yf = floorf(y);
            const int x0 = (int)xf;
            const int y0 = (int)yf;
            const int x1 = x0 + 1;
            const int y1 = y0 + 1;

            float wx1 = x - xf;
            float wx0 = 1.0f - wx1;
            float wy1 = y - yf;
            float wy0 = 1.0f - wy1;

            if (x0 < 0 || x0 > W - 1) wx0 = 0.0f;
            if (x1 < 0 || x1 > W - 1) wx1 = 0.0f;
            if (y0 < 0 || y0 > H - 1) wy0 = 0.0f;
            if (y1 < 0 || y1 > H - 1) wy1 = 0.0f;
            const int x0c = min(max(x0, 0), W - 1);
            const int x1c = min(max(x1, 0), W - 1);
            const int y0c = min(max(y0, 0), H - 1);
            const int y1c = min(max(y1, 0), H - 1);

            w00[lvl] = w * wx0 * wy0;
            w10[lvl] = w * wx1 * wy0;
            w01[lvl] = w * wx0 * wy1;
            w11[lvl] = w * wx1 * wy1;

            const int r0 = bases[lvl] + y0c * W;
            const int r1 = bases[lvl] + y1c * W;
            o00[lvl] = (r0 + x0c) * mult;
            o10[lvl] = (r0 + x1c) * mult;
            o01[lvl] = (r1 + x0c) * mult;
            o11[lvl] = (r1 + x1c) * mult;
        }

        // ---------------- Phase B: gather + accumulate ----------------
        float4 acc = make_float4(0.f, 0.f, 0.f, 0.f);

        #pragma unroll
        for (int lvl = 0; lvl < NL; ++lvl) {
            float4 a, c, d, e;
            if (lvl < 2) {
                a = __ldg(v4 + o00[lvl]);
                c = __ldg(v4 + o10[lvl]);
                d = __ldg(v4 + o01[lvl]);
                e = __ldg(v4 + o11[lvl]);
            } else {
                a = s4[o00[lvl] + cp];
                c = s4[o10[lvl] + cp];
                d = s4[o01[lvl] + cp];
                e = s4[o11[lvl] + cp];
            }
            const float wa = w00[lvl], wc = w10[lvl], wd = w01[lvl], we = w11[lvl];

            acc.x += a.x * wa + c.x * wc + d.x * wd + e.x * we;
            acc.y += a.y * wa + c.y * wc + d.y * wd + e.y * we;
            acc.z += a.z * wa + c.z * wc + d.z * wd + e.z * we;
            acc.w += a.w * wa + c.w * wc + d.w * wd + e.w * we;
        }

        #pragma unroll
        for (int m = 8; m <= 16; m <<= 1) {
            acc.x += __shfl_xor_sync(0xffffffffu, acc.x, m);
            acc.y += __shfl_xor_sync(0xffffffffu, acc.y, m);
            acc.z += __shfl_xor_sync(0xffffffffu, acc.z, m);
            acc.w += __shfl_xor_sync(0xffffffffu, acc.w, m);
        }

        if (g == 0) {
            ((float4*)out)[(size_t)task * (DC / 4) + cp] = acc;
        }
    }
}

extern "C" void kernel_launch(void* const* d_in, const int* in_sizes, int n_in,
                              void* d_out, int out_size)
{
    const float* value = (const float*)d_in[0];
    const float* loc   = (const float*)d_in[1];
    const float* aw    = (const float*)d_in[2];
    float* out         = (float*)d_out;

    const int smem_bytes = SMEM_F4 * 16;   // 169344
    static int attr_set = 0;
    if (!attr_set) {
        cudaFuncSetAttribute(msda_kernel,
                             cudaFuncAttributeMaxDynamicSharedMemorySize,
                             smem_bytes);
        attr_set = 1;
    }

    msda_kernel<<<BS * NH * 2, 1024, smem_bytes>>>(value, loc, aw, out);
}

// round 9
// speedup vs baseline: 1.0965x; 1.0965x over previous
#include <cuda_runtime.h>
#include <cstdint>

// MultiScaleDeformableAttention — GB300
// value:              (8, 22223, 8, 32)  float32
// sampling_locations: (8, 900, 8, 4, 4, 2) float32
// attention_weights:  (8, 900, 8, 4, 4) float32
// out:                (8, 900, 256) float32
//
// Strategy: CTA pinned to one (b,h) (grid = 64 x 2 halves = 128 CTAs x 1024
// threads) so the level-2/3 value planes (169KB per (b,h)) are L1D-resident
// (228KB, no smem carveout). Streaming traffic (lvl-0/1 taps, loc, aw) is
// loaded with __ldcs (evict-first) so it cannot thrash those resident lines;
// lvl-2/3 taps use default caching (__ldg). No shared memory at all.
// Per-warp body = best R4 form: lane=(g,cp), 16 branch-free tap descriptors,
// then 16 unconditional 128-bit loads + FMA, shfl_xor reduction.

#define BS  8
#define NQ  900
#define NH  8
#define DC  32
#define NL  4
#define NPT 4
#define NKEYS 22223
#define KS4 (NH * DC / 4)        // float4s per key = 64
#define QHALF (NQ / 2)           // 450 queries per CTA

__global__ __launch_bounds__(1024, 1) void msda_kernel(
    const float* __restrict__ value,
    const float* __restrict__ loc,
    const float* __restrict__ aw,
    float* __restrict__ out)
{
    const int Hs[NL]     = {100, 50, 25, 13};
    const int Ws[NL]     = {167, 84, 42, 21};
    const int starts[NL] = {0, 16700, 20900, 21950};

    const int bh   = blockIdx.x >> 1;    // 0..63
    const int half = blockIdx.x & 1;
    const int b    = bh >> 3;
    const int h    = bh & (NH - 1);

    const int tid  = threadIdx.x;
    const int wid  = tid >> 5;
    const int lane = tid & 31;
    const int g  = lane >> 3;            // point within level (0..3)
    const int cp = lane & 7;             // channel quad (0..7)

    const float4* __restrict__ v4 =
        (const float4*)value + ((size_t)(b * NKEYS) * NH + h) * (DC / 4) + cp;
    const float2* __restrict__ loc2 = (const float2*)loc;

    for (int ql = wid; ql < QHALF; ql += 32) {
        const int q    = half * QHALF + ql;
        const int task = (b * NQ + q) * NH + h;

        // ---------------- Phase A: tap descriptors ----------------
        int   o00[NL], o10[NL], o01[NL], o11[NL];
        float w00[NL], w10[NL], w01[NL], w11[NL];

        #pragma unroll
        for (int lvl = 0; lvl < NL; ++lvl) {
            const int H = Hs[lvl];
            const int W = Ws[lvl];
            const int start = starts[lvl];

            const int li = (task * NL + lvl) * NPT + g;
            const float2 l2 = __ldcs(loc2 + li);   // streaming: evict-first
            const float w   = __ldcs(aw + li);

            const float x = l2.x * (float)W - 0.5f;
            const float y = l2.y * (float)H - 0.5f;
            const float xf = floorf(x);
            const float yf = floorf(y);
            const int x0 = (int)xf;
            const int y0 = (int)yf;
            const int x1 = x0 + 1;
            const int y1 = y0 + 1;

            float wx1 = x - xf;
            float wx0 = 1.0f - wx1;
            float wy1 = y - yf;
            float wy0 = 1.0f - wy1;

            // branch-free OOB: clamp index, zero the edge weight
            if (x0 < 0 || x0 > W - 1) wx0 = 0.0f;
            if (x1 < 0 || x1 > W - 1) wx1 = 0.0f;
            if (y0 < 0 || y0 > H - 1) wy0 = 0.0f;
            if (y1 < 0 || y1 > H - 1) wy1 = 0.0f;
            const int x0c = min(max(x0, 0), W - 1);
            const int x1c = min(max(x1, 0), W - 1);
            const int y0c = min(max(y0, 0), H - 1);
            const int y1c = min(max(y1, 0), H - 1);

            w00[lvl] = w * wx0 * wy0;
            w10[lvl] = w * wx1 * wy0;
            w01[lvl] = w * wx0 * wy1;
            w11[lvl] = w * wx1 * wy1;

            const int r0 = start + y0c * W;
            const int r1 = start + y1c * W;
            o00[lvl] = (r0 + x0c) * KS4;
            o10[lvl] = (r0 + x1c) * KS4;
            o01[lvl] = (r1 + x0c) * KS4;
            o11[lvl] = (r1 + x1c) * KS4;
        }

        // ---------------- Phase B: gather + accumulate ----------------
        float4 acc = make_float4(0.f, 0.f, 0.f, 0.f);

        #pragma unroll
        for (int lvl = 0; lvl < NL; ++lvl) {
            float4 a, c, d, e;
            if (lvl < 2) {
                // streaming levels: evict-first, don't thrash L1
                a = __ldcs(v4 + o00[lvl]);
                c = __ldcs(v4 + o10[lvl]);
                d = __ldcs(v4 + o01[lvl]);
                e = __ldcs(v4 + o11[lvl]);
            } else {
                // small levels: cache-all, stay L1-resident (169KB/bh < 228KB)
                a = __ldg(v4 + o00[lvl]);
                c = __ldg(v4 + o10[lvl]);
                d = __ldg(v4 + o01[lvl]);
                e = __ldg(v4 + o11[lvl]);
            }
            const float wa = w00[lvl], wc = w10[lvl], wd = w01[lvl], we = w11[lvl];

            acc.x += a.x * wa + c.x * wc + d.x * wd + e.x * we;
            acc.y += a.y * wa + c.y * wc + d.y * wd + e.y * we;
            acc.z += a.z * wa + c.z * wc + d.z * wd + e.z * we;
            acc.w += a.w * wa + c.w * wc + d.w * wd + e.w * we;
        }

        // reduce the 4 point-groups (lanes cp, cp+8, cp+16, cp+24)
        #pragma unroll
        for (int m = 8; m <= 16; m <<= 1) {
            acc.x += __shfl_xor_sync(0xffffffffu, acc.x, m);
            acc.y += __shfl_xor_sync(0xffffffffu, acc.y, m);
            acc.z += __shfl_xor_sync(0xffffffffu, acc.z, m);
            acc.w += __shfl_xor_sync(0xffffffffu, acc.w, m);
        }

        if (g == 0) {
            ((float4*)out)[(size_t)task * (DC / 4) + cp] = acc;
        }
    }
}

extern "C" void kernel_launch(void* const* d_in, const int* in_sizes, int n_in,
                              void* d_out, int out_size)
{
    const float* value = (const float*)d_in[0];
    const float* loc   = (const float*)d_in[1];
    const float* aw    = (const float*)d_in[2];
    float* out         = (float*)d_out;

    // 64 (b,h) pairs x 2 query-halves = 128 CTAs, one per SM
    msda_kernel<<<BS * NH * 2, 1024>>>(value, loc, aw, out);
}